// round 5
// baseline (speedup 1.0000x reference)
#include <cuda_runtime.h>
#include <cuda_bf16.h>
#include <cstdint>

#define H 512
#define O 512
#define E 16
#define N_MAX 32768

#define BM 128          // tokens per CTA tile
#define BN 128          // outputs per CTA tile
#define BKT 64          // bf16 k-elements per smem tile (128B per row)
#define KTILES (H / BKT)
#define MAX_TILES 272

// ---------------- device scratch ----------------
__device__ int g_eidx[N_MAX];
__device__ int g_count[E];
__device__ int g_offset[E];
__device__ int g_cursor[E];
__device__ int g_perm[N_MAX];
__device__ int g_tile_e[MAX_TILES];
__device__ int g_tile_m0[MAX_TILES];
__device__ int g_ntiles;

// pre-split bf16 hi/lo copies (hi = rn(x), lo = rn(x - hi))
__device__ uint16_t g_xhi[N_MAX * H];   // 32 MB
__device__ uint16_t g_xlo[N_MAX * H];   // 32 MB
__device__ uint16_t g_whi[E * O * H];   // 8 MB
__device__ uint16_t g_wlo[E * O * H];   // 8 MB

// ---------------- helpers ----------------
__device__ __forceinline__ uint32_t smem_u32(const void* p) {
    uint32_t a;
    asm("{ .reg .u64 t; cvta.to.shared.u64 t, %1; cvt.u32.u64 %0, t; }" : "=r"(a) : "l"(p));
    return a;
}
#define SWZ(o) ((o) ^ (((o) >> 3) & 0x70))

// fp32 pair -> bf16 hi pair + bf16 lo pair. low 16 bits = first elem.
__device__ __forceinline__ void cvt_split(float a, float b, uint32_t& hi, uint32_t& lo) {
    asm("cvt.rn.satfinite.bf16x2.f32 %0, %1, %2;" : "=r"(hi) : "f"(b), "f"(a));
    float ha = __uint_as_float(hi << 16);
    float hb = __uint_as_float(hi & 0xffff0000u);
    float ra = a - ha, rb = b - hb;
    asm("cvt.rn.satfinite.bf16x2.f32 %0, %1, %2;" : "=r"(lo) : "f"(rb), "f"(ra));
}

__device__ __forceinline__ void ldsm4(uint32_t* r, uint32_t addr) {
    asm volatile("ldmatrix.sync.aligned.m8n8.x4.shared.b16 {%0,%1,%2,%3}, [%4];"
                 : "=r"(r[0]), "=r"(r[1]), "=r"(r[2]), "=r"(r[3]) : "r"(addr));
}

__device__ __forceinline__ void mma_bf16(float* d, const uint32_t* a, const uint32_t* b) {
    asm volatile(
        "mma.sync.aligned.m16n8k16.row.col.f32.bf16.bf16.f32 "
        "{%0,%1,%2,%3}, {%4,%5,%6,%7}, {%8,%9}, {%0,%1,%2,%3};"
        : "+f"(d[0]), "+f"(d[1]), "+f"(d[2]), "+f"(d[3])
        : "r"(a[0]), "r"(a[1]), "r"(a[2]), "r"(a[3]), "r"(b[0]), "r"(b[1]));
}

// 16B async copy, src_size=0 -> zero-fill
__device__ __forceinline__ void cp16(uint32_t dst, const void* src, int srcsz) {
    asm volatile("cp.async.cg.shared.global [%0], [%1], 16, %2;"
                 :: "r"(dst), "l"(src), "r"(srcsz) : "memory");
}
#define CP_COMMIT() asm volatile("cp.async.commit_group;" ::: "memory")
#define CP_WAIT(n)  asm volatile("cp.async.wait_group %0;" :: "n"(n) : "memory")

// ---------------- smem layout ----------------
// [0,512) rows, [512,1024) bias, [1024,+2*64K) double buffer {A_hi,A_lo,B_hi,B_lo} x16KB
#define BUF_SZ 65536
#define A_HI 0
#define A_LO 16384
#define B_HI 32768
#define B_LO 49152
#define SMEM_TOTAL (1024 + 2 * BUF_SZ)

// ---------------- stage 0 ----------------
__global__ void init_kernel() {
    int t = threadIdx.x;
    if (t < E) g_count[t] = 0;
}

// ---------------- stage 0b: split We -> bf16 hi/lo ----------------
__global__ void wsplit_kernel(const float* __restrict__ We) {
    int i = (blockIdx.x * blockDim.x + threadIdx.x) * 4;  // element index
    if (i >= E * O * H) return;
    float4 v = *(const float4*)(We + i);
    uint32_t h01, l01, h23, l23;
    cvt_split(v.x, v.y, h01, l01);
    cvt_split(v.z, v.w, h23, l23);
    *(uint2*)(g_whi + i) = make_uint2(h01, h23);
    *(uint2*)(g_wlo + i) = make_uint2(l01, l23);
}

// ---------------- stage 1: gate + x split ----------------
__global__ void gate_kernel(const float* __restrict__ x, const float* __restrict__ Wg,
                            const float* __restrict__ bg, int n_tokens) {
    __shared__ float Wgs[E * H];
    int t = threadIdx.x;
    for (int i = t; i < E * H; i += blockDim.x) Wgs[i] = Wg[i];
    __syncthreads();

    int n = blockIdx.x * blockDim.x + t;
    if (n >= n_tokens) return;
    const float* xr = x + (size_t)n * H;

    float acc[E];
#pragma unroll
    for (int e = 0; e < E; e++) acc[e] = bg[e];

    for (int k = 0; k < H; k += 4) {
        float4 xv = *(const float4*)(xr + k);
        // split + store bf16 hi/lo copies of x (reuses the load)
        uint32_t h01, l01, h23, l23;
        cvt_split(xv.x, xv.y, h01, l01);
        cvt_split(xv.z, xv.w, h23, l23);
        *(uint2*)(g_xhi + (size_t)n * H + k) = make_uint2(h01, h23);
        *(uint2*)(g_xlo + (size_t)n * H + k) = make_uint2(l01, l23);
#pragma unroll
        for (int e = 0; e < E; e++) {
            float4 w = *(const float4*)(&Wgs[e * H + k]);
            acc[e] += xv.x * w.x + xv.y * w.y + xv.z * w.z + xv.w * w.w;
        }
    }

    int best = 0;
    float bv = acc[0];
#pragma unroll
    for (int e = 1; e < E; e++)
        if (acc[e] > bv) { bv = acc[e]; best = e; }

    int sec = (best == 0) ? 1 : 0;
    float sv = acc[sec];
#pragma unroll
    for (int e = 0; e < E; e++)
        if (e != best && acc[e] > sv) { sv = acc[e]; sec = e; }

    if (bv - sv < 1e-3f) {
        int ea = min(best, sec), eb = max(best, sec);
        double la = (double)bg[ea], lb = (double)bg[eb];
        for (int k = 0; k < H; k++) {
            double xv = (double)xr[k];
            la += xv * (double)Wgs[ea * H + k];
            lb += xv * (double)Wgs[eb * H + k];
        }
        best = (lb > la) ? eb : ea;  // first-occurrence tie-break
    }

    g_eidx[n] = best;
    atomicAdd(&g_count[best], 1);
}

// ---------------- stage 2: scan + tile table ----------------
__global__ void scan_kernel() {
    if (threadIdx.x != 0) return;
    int s = 0, tc = 0;
    for (int e = 0; e < E; e++) {
        g_offset[e] = s;
        g_cursor[e] = s;
        int c = g_count[e];
        s += c;
        for (int m0 = 0; m0 < c; m0 += BM) {
            g_tile_e[tc] = e;
            g_tile_m0[tc] = m0;
            tc++;
        }
    }
    g_ntiles = tc;
}

// ---------------- stage 3: scatter ----------------
__global__ void scatter_kernel(int n_tokens) {
    int n = blockIdx.x * blockDim.x + threadIdx.x;
    if (n >= n_tokens) return;
    int e = g_eidx[n];
    int slot = atomicAdd(&g_cursor[e], 1);
    g_perm[slot] = n;
}

// ---------------- stage 4: HMMA gather-GEMM, cp.async pipeline ----------------
__global__ __launch_bounds__(256, 1) void expert_gemm(const float* __restrict__ be,
                                                      float* __restrict__ out) {
    int tile = blockIdx.y;
    if (tile >= g_ntiles) return;
    int t = threadIdx.x;
    int e = g_tile_e[tile];
    int m0 = g_tile_m0[tile];
    int cnt = g_count[e];
    int base = g_offset[e];
    int n0 = blockIdx.x * BN;

    extern __shared__ char smem[];
    int* rows = (int*)smem;
    float* bias_s = (float*)(smem + 512);
    uint32_t sb = smem_u32(smem);

    if (t < BM) {
        int m = m0 + t;
        rows[t] = (m < cnt) ? g_perm[base + m] : -1;
        bias_s[t] = be[e * O + n0 + t];
    }
    __syncthreads();

    // ---- loader: thread t owns chunks c = t + g*256, g<4; row=c>>3, ch=c&7 ----
    const uint16_t* pAh[4];
    const uint16_t* pAl[4];
    const uint16_t* pBh[4];
    const uint16_t* pBl[4];
    int szA[4];
    uint32_t dsw[4];
#pragma unroll
    for (int g = 0; g < 4; g++) {
        int c = t + g * 256;
        int row = c >> 3, ch = c & 7;
        int r = rows[row];
        szA[g] = (r >= 0) ? 16 : 0;
        size_t aoff = (size_t)(r < 0 ? 0 : r) * H + ch * 8;
        pAh[g] = g_xhi + aoff;
        pAl[g] = g_xlo + aoff;
        size_t boff = (size_t)(e * O + n0 + row) * H + ch * 8;
        pBh[g] = g_whi + boff;
        pBl[g] = g_wlo + boff;
        dsw[g] = SWZ((uint32_t)(row * 128 + ch * 16));
    }

#define ISSUE_TILE(kt, bufbase)                                     \
    {                                                               \
        int koff = (kt) * BKT;                                      \
        _Pragma("unroll") for (int g = 0; g < 4; g++) {             \
            cp16((bufbase) + A_HI + dsw[g], pAh[g] + koff, szA[g]); \
            cp16((bufbase) + A_LO + dsw[g], pAl[g] + koff, szA[g]); \
            cp16((bufbase) + B_HI + dsw[g], pBh[g] + koff, 16);     \
            cp16((bufbase) + B_LO + dsw[g], pBl[g] + koff, 16);     \
        }                                                           \
        CP_COMMIT();                                                \
    }

    // ---- warp tiling: 8 warps = 4m x 2n, warp tile 32x64 ----
    int w = t >> 5, lane = t & 31;
    int warpM = w & 3, warpN = w >> 2;
    int grp = lane >> 3, lr = lane & 7;
    int arow = lr + (grp & 1) * 8;
    int akc = (grp >> 1) * 8;
    int brow = (grp >> 1) * 8 + lr;
    int bkc = (grp & 1) * 8;

    float acc[2][8][4];
#pragma unroll
    for (int i = 0; i < 2; i++)
#pragma unroll
        for (int j = 0; j < 8; j++)
#pragma unroll
            for (int c = 0; c < 4; c++) acc[i][j][c] = 0.f;

    uint32_t buf0 = sb + 1024, buf1 = sb + 1024 + BUF_SZ;

    ISSUE_TILE(0, buf0);

    for (int kt = 0; kt < KTILES; kt++) {
        uint32_t bufb = (kt & 1) ? buf1 : buf0;
        if (kt + 1 < KTILES) {
            ISSUE_TILE(kt + 1, (kt & 1) ? buf0 : buf1);
            CP_WAIT(1);
        } else {
            CP_WAIT(0);
        }
        __syncthreads();  // tile kt visible to all

#pragma unroll
        for (int ks = 0; ks < 4; ks++) {
            uint32_t ah[2][4], al[2][4], bh[4][4], bl[4][4];
#pragma unroll
            for (int mi = 0; mi < 2; mi++) {
                uint32_t off = SWZ((uint32_t)((warpM * 32 + mi * 16 + arow) * 128 +
                                              (ks * 16 + akc) * 2));
                ldsm4(ah[mi], bufb + A_HI + off);
                ldsm4(al[mi], bufb + A_LO + off);
            }
#pragma unroll
            for (int njp = 0; njp < 4; njp++) {
                uint32_t off = SWZ((uint32_t)((warpN * 64 + njp * 16 + brow) * 128 +
                                              (ks * 16 + bkc) * 2));
                ldsm4(bh[njp], bufb + B_HI + off);
                ldsm4(bl[njp], bufb + B_LO + off);
            }
#pragma unroll
            for (int mi = 0; mi < 2; mi++)
#pragma unroll
                for (int njp = 0; njp < 4; njp++) {
                    mma_bf16(acc[mi][njp * 2],     ah[mi], &bh[njp][0]);
                    mma_bf16(acc[mi][njp * 2 + 1], ah[mi], &bh[njp][2]);
                    mma_bf16(acc[mi][njp * 2],     ah[mi], &bl[njp][0]);
                    mma_bf16(acc[mi][njp * 2 + 1], ah[mi], &bl[njp][2]);
                    mma_bf16(acc[mi][njp * 2],     al[mi], &bh[njp][0]);
                    mma_bf16(acc[mi][njp * 2 + 1], al[mi], &bh[njp][2]);
                }
        }
        __syncthreads();  // all reads of buf kt done before it is refilled
    }

    // ---- epilogue: acc + bias -> gathered token rows ----
    int qrow = lane >> 2, qcol = lane & 3;
#pragma unroll
    for (int mi = 0; mi < 2; mi++)
#pragma unroll
        for (int h = 0; h < 2; h++) {
            int m = warpM * 32 + mi * 16 + h * 8 + qrow;
            int r = rows[m];
            if (r < 0) continue;
            float* orow = out + (size_t)r * O + n0 + warpN * 64;
#pragma unroll
            for (int nj = 0; nj < 8; nj++) {
                int col = nj * 8 + qcol * 2;
                float2 o;
                o.x = acc[mi][nj][h * 2]     + bias_s[warpN * 64 + col];
                o.y = acc[mi][nj][h * 2 + 1] + bias_s[warpN * 64 + col + 1];
                *(float2*)(orow + col) = o;
            }
        }
}

// ---------------- launch ----------------
extern "C" void kernel_launch(void* const* d_in, const int* in_sizes, int n_in,
                              void* d_out, int out_size) {
    const float* x  = (const float*)d_in[0];  // [N, H]
    const float* Wg = (const float*)d_in[1];  // [E, H]
    const float* bg = (const float*)d_in[2];  // [E]
    const float* We = (const float*)d_in[3];  // [E, O, H]
    const float* be = (const float*)d_in[4];  // [E, O]
    float* out = (float*)d_out;               // [N, O]

    int n_tokens = in_sizes[0] / H;

    cudaFuncSetAttribute(expert_gemm, cudaFuncAttributeMaxDynamicSharedMemorySize,
                         SMEM_TOTAL);

    init_kernel<<<1, 32>>>();
    wsplit_kernel<<<(E * O * H / 4 + 255) / 256, 256>>>(We);
    gate_kernel<<<(n_tokens + 255) / 256, 256>>>(x, Wg, bg, n_tokens);
    scan_kernel<<<1, 32>>>();
    scatter_kernel<<<(n_tokens + 255) / 256, 256>>>(n_tokens);

    dim3 grid(O / BN, MAX_TILES);
    expert_gemm<<<grid, 256, SMEM_TOTAL>>>(be, out);
}

// round 6
// speedup vs baseline: 1.1545x; 1.1545x over previous
#include <cuda_runtime.h>
#include <cuda_fp16.h>
#include <cstdint>

#define H 512
#define O 512
#define E 16
#define N_MAX 32768

#define BM 128          // tokens per CTA tile
#define BN 128          // outputs per CTA tile
#define BKT 64          // fp16 k-elements per smem tile (128B per row)
#define KTILES (H / BKT)
#define MAX_TILES 272

// ---------------- device scratch ----------------
__device__ int g_eidx[N_MAX];
__device__ int g_count[E];
__device__ int g_offset[E];
__device__ int g_cursor[E];
__device__ int g_perm[N_MAX];
__device__ int g_tile_e[MAX_TILES];
__device__ int g_tile_m0[MAX_TILES];
__device__ int g_ntiles;

// pre-split fp16 copies: x = xhi + xlo (22-bit effective), W = whi (11-bit)
__device__ uint16_t g_xhi[N_MAX * H];   // 32 MB
__device__ uint16_t g_xlo[N_MAX * H];   // 32 MB
__device__ uint16_t g_whi[E * O * H];   // 8 MB

// ---------------- helpers ----------------
__device__ __forceinline__ uint32_t smem_u32(const void* p) {
    uint32_t a;
    asm("{ .reg .u64 t; cvta.to.shared.u64 t, %1; cvt.u32.u64 %0, t; }" : "=r"(a) : "l"(p));
    return a;
}
#define SWZ(o) ((o) ^ (((o) >> 3) & 0x70))

// fp32 pair -> fp16 hi pair (low 16 bits = first elem)
__device__ __forceinline__ uint32_t cvt_h2(float a, float b) {
    uint32_t hi;
    asm("cvt.rn.f16x2.f32 %0, %1, %2;" : "=r"(hi) : "f"(b), "f"(a));
    return hi;
}
// fp32 pair -> fp16 hi pair + fp16 lo (residual) pair
__device__ __forceinline__ void cvt_split_h(float a, float b, uint32_t& hi, uint32_t& lo) {
    hi = cvt_h2(a, b);
    __half2 h2 = *reinterpret_cast<__half2*>(&hi);
    float2 hf = __half22float2(h2);
    lo = cvt_h2(a - hf.x, b - hf.y);
}

__device__ __forceinline__ void ldsm4(uint32_t* r, uint32_t addr) {
    asm volatile("ldmatrix.sync.aligned.m8n8.x4.shared.b16 {%0,%1,%2,%3}, [%4];"
                 : "=r"(r[0]), "=r"(r[1]), "=r"(r[2]), "=r"(r[3]) : "r"(addr));
}

__device__ __forceinline__ void mma_f16(float* d, const uint32_t* a, const uint32_t* b) {
    asm volatile(
        "mma.sync.aligned.m16n8k16.row.col.f32.f16.f16.f32 "
        "{%0,%1,%2,%3}, {%4,%5,%6,%7}, {%8,%9}, {%0,%1,%2,%3};"
        : "+f"(d[0]), "+f"(d[1]), "+f"(d[2]), "+f"(d[3])
        : "r"(a[0]), "r"(a[1]), "r"(a[2]), "r"(a[3]), "r"(b[0]), "r"(b[1]));
}

// 16B async copy, src_size=0 -> zero-fill
__device__ __forceinline__ void cp16(uint32_t dst, const void* src, int srcsz) {
    asm volatile("cp.async.cg.shared.global [%0], [%1], 16, %2;"
                 :: "r"(dst), "l"(src), "r"(srcsz) : "memory");
}
#define CP_COMMIT() asm volatile("cp.async.commit_group;" ::: "memory")
#define CP_WAIT(n)  asm volatile("cp.async.wait_group %0;" :: "n"(n) : "memory")

// ---------------- smem layout ----------------
// [0,512) rows, [512,1024) bias, then 3 stages of {A_hi 16K, A_lo 16K, B_hi 16K}
#define STAGE_SZ 49152
#define A_HI 0
#define A_LO 16384
#define B_HI 32768
#define SMEM_TOTAL (1024 + 3 * STAGE_SZ)

// ---------------- stage 0: zero counts + split We -> fp16 hi ----------------
__global__ void prep_kernel(const float* __restrict__ We) {
    int idx = blockIdx.x * blockDim.x + threadIdx.x;
    if (idx < E) g_count[idx] = 0;
    int i = idx * 4;
    if (i < E * O * H) {
        float4 v = *(const float4*)(We + i);
        *(uint2*)(g_whi + i) = make_uint2(cvt_h2(v.x, v.y), cvt_h2(v.z, v.w));
    }
}

// ---------------- stage 1: gate + x split ----------------
__global__ void gate_kernel(const float* __restrict__ x, const float* __restrict__ Wg,
                            const float* __restrict__ bg, int n_tokens) {
    __shared__ float Wgs[E * H];
    int t = threadIdx.x;
    for (int i = t; i < E * H; i += blockDim.x) Wgs[i] = Wg[i];
    __syncthreads();

    int n = blockIdx.x * blockDim.x + t;
    if (n >= n_tokens) return;
    const float* xr = x + (size_t)n * H;

    float acc[E];
#pragma unroll
    for (int e = 0; e < E; e++) acc[e] = bg[e];

    for (int k = 0; k < H; k += 4) {
        float4 xv = *(const float4*)(xr + k);
        uint32_t h01, l01, h23, l23;
        cvt_split_h(xv.x, xv.y, h01, l01);
        cvt_split_h(xv.z, xv.w, h23, l23);
        *(uint2*)(g_xhi + (size_t)n * H + k) = make_uint2(h01, h23);
        *(uint2*)(g_xlo + (size_t)n * H + k) = make_uint2(l01, l23);
#pragma unroll
        for (int e = 0; e < E; e++) {
            float4 w = *(const float4*)(&Wgs[e * H + k]);
            acc[e] += xv.x * w.x + xv.y * w.y + xv.z * w.z + xv.w * w.w;
        }
    }

    int best = 0;
    float bv = acc[0];
#pragma unroll
    for (int e = 1; e < E; e++)
        if (acc[e] > bv) { bv = acc[e]; best = e; }

    int sec = (best == 0) ? 1 : 0;
    float sv = acc[sec];
#pragma unroll
    for (int e = 0; e < E; e++)
        if (e != best && acc[e] > sv) { sv = acc[e]; sec = e; }

    if (bv - sv < 1e-3f) {
        int ea = min(best, sec), eb = max(best, sec);
        double la = (double)bg[ea], lb = (double)bg[eb];
        for (int k = 0; k < H; k++) {
            double xv = (double)xr[k];
            la += xv * (double)Wgs[ea * H + k];
            lb += xv * (double)Wgs[eb * H + k];
        }
        best = (lb > la) ? eb : ea;  // first-occurrence tie-break
    }

    g_eidx[n] = best;
    atomicAdd(&g_count[best], 1);
}

// ---------------- stage 2: warp-parallel scan + tile table ----------------
__global__ void scan_kernel() {
    int lane = threadIdx.x;
    int c = (lane < E) ? g_count[lane] : 0;
    int nt = (c + BM - 1) / BM;
    int sc = c, snt = nt;
#pragma unroll
    for (int d = 1; d < 32; d <<= 1) {
        int vc = __shfl_up_sync(0xFFFFFFFFu, sc, d);
        int vn = __shfl_up_sync(0xFFFFFFFFu, snt, d);
        if (lane >= d) { sc += vc; snt += vn; }
    }
    int off = sc - c;
    int toff = snt - nt;
    if (lane < E) {
        g_offset[lane] = off;
        g_cursor[lane] = off;
        for (int i = 0; i < nt; i++) {
            g_tile_e[toff + i] = lane;
            g_tile_m0[toff + i] = i * BM;
        }
    }
    if (lane == 31) g_ntiles = snt;
}

// ---------------- stage 3: scatter ----------------
__global__ void scatter_kernel(int n_tokens) {
    int n = blockIdx.x * blockDim.x + threadIdx.x;
    if (n >= n_tokens) return;
    int e = g_eidx[n];
    int slot = atomicAdd(&g_cursor[e], 1);
    g_perm[slot] = n;
}

// ---------------- stage 4: HMMA gather-GEMM, fp16 2-term, 3-stage pipeline ----
__global__ __launch_bounds__(256, 1) void expert_gemm(const float* __restrict__ be,
                                                      float* __restrict__ out) {
    int tile = blockIdx.y;
    if (tile >= g_ntiles) return;
    int t = threadIdx.x;
    int e = g_tile_e[tile];
    int m0 = g_tile_m0[tile];
    int cnt = g_count[e];
    int base = g_offset[e];
    int n0 = blockIdx.x * BN;

    extern __shared__ char smem[];
    int* rows = (int*)smem;
    float* bias_s = (float*)(smem + 512);
    uint32_t sb = smem_u32(smem);

    if (t < BM) {
        int m = m0 + t;
        rows[t] = (m < cnt) ? g_perm[base + m] : -1;
        bias_s[t] = be[e * O + n0 + t];
    }
    __syncthreads();

    // ---- loader: thread t owns chunks c = t + g*256, g<4; row=c>>3, ch=c&7 ----
    const uint16_t* pAh[4];
    const uint16_t* pAl[4];
    const uint16_t* pBh[4];
    int szA[4];
    uint32_t dsw[4];
#pragma unroll
    for (int g = 0; g < 4; g++) {
        int c = t + g * 256;
        int row = c >> 3, ch = c & 7;
        int r = rows[row];
        szA[g] = (r >= 0) ? 16 : 0;
        size_t aoff = (size_t)(r < 0 ? 0 : r) * H + ch * 8;
        pAh[g] = g_xhi + aoff;
        pAl[g] = g_xlo + aoff;
        pBh[g] = g_whi + (size_t)(e * O + n0 + row) * H + ch * 8;
        dsw[g] = SWZ((uint32_t)(row * 128 + ch * 16));
    }

#define ISSUE_TILE(kt, bufbase)                                     \
    {                                                               \
        int koff = (kt) * BKT;                                      \
        _Pragma("unroll") for (int g = 0; g < 4; g++) {             \
            cp16((bufbase) + A_HI + dsw[g], pAh[g] + koff, szA[g]); \
            cp16((bufbase) + A_LO + dsw[g], pAl[g] + koff, szA[g]); \
            cp16((bufbase) + B_HI + dsw[g], pBh[g] + koff, 16);     \
        }                                                           \
        CP_COMMIT();                                                \
    }

    // ---- warp tiling: 8 warps = 4m x 2n, warp tile 32x64 ----
    int w = t >> 5, lane = t & 31;
    int warpM = w & 3, warpN = w >> 2;
    int grp = lane >> 3, lr = lane & 7;
    int arow = lr + (grp & 1) * 8;
    int akc = (grp >> 1) * 8;
    int brow = (grp >> 1) * 8 + lr;
    int bkc = (grp & 1) * 8;

    float acc[2][8][4];
#pragma unroll
    for (int i = 0; i < 2; i++)
#pragma unroll
        for (int j = 0; j < 8; j++)
#pragma unroll
            for (int c = 0; c < 4; c++) acc[i][j][c] = 0.f;

    uint32_t bufs[3] = {sb + 1024, sb + 1024 + STAGE_SZ, sb + 1024 + 2 * STAGE_SZ};

    ISSUE_TILE(0, bufs[0]);
    ISSUE_TILE(1, bufs[1]);

    for (int kt = 0; kt < KTILES; kt++) {
        if (kt == KTILES - 1) { CP_WAIT(0); } else { CP_WAIT(1); }
        __syncthreads();  // tile kt visible; all reads of buf[(kt+2)%3] (iter kt-1) done
        if (kt + 2 < KTILES) ISSUE_TILE(kt + 2, bufs[(kt + 2) % 3]);

        uint32_t bufb = bufs[kt % 3];
#pragma unroll
        for (int ks = 0; ks < 4; ks++) {
            uint32_t ah[2][4], al[2][4], bh[4][4];
#pragma unroll
            for (int mi = 0; mi < 2; mi++) {
                uint32_t off = SWZ((uint32_t)((warpM * 32 + mi * 16 + arow) * 128 +
                                              (ks * 16 + akc) * 2));
                ldsm4(ah[mi], bufb + A_HI + off);
                ldsm4(al[mi], bufb + A_LO + off);
            }
#pragma unroll
            for (int njp = 0; njp < 4; njp++) {
                uint32_t off = SWZ((uint32_t)((warpN * 64 + njp * 16 + brow) * 128 +
                                              (ks * 16 + bkc) * 2));
                ldsm4(bh[njp], bufb + B_HI + off);
            }
#pragma unroll
            for (int mi = 0; mi < 2; mi++)
#pragma unroll
                for (int njp = 0; njp < 4; njp++) {
                    mma_f16(acc[mi][njp * 2],     ah[mi], &bh[njp][0]);
                    mma_f16(acc[mi][njp * 2 + 1], ah[mi], &bh[njp][2]);
                    mma_f16(acc[mi][njp * 2],     al[mi], &bh[njp][0]);
                    mma_f16(acc[mi][njp * 2 + 1], al[mi], &bh[njp][2]);
                }
        }
    }

    // ---- epilogue: acc + bias -> gathered token rows ----
    int qrow = lane >> 2, qcol = lane & 3;
#pragma unroll
    for (int mi = 0; mi < 2; mi++)
#pragma unroll
        for (int h = 0; h < 2; h++) {
            int m = warpM * 32 + mi * 16 + h * 8 + qrow;
            int r = rows[m];
            if (r < 0) continue;
            float* orow = out + (size_t)r * O + n0 + warpN * 64;
#pragma unroll
            for (int nj = 0; nj < 8; nj++) {
                int col = nj * 8 + qcol * 2;
                float2 o;
                o.x = acc[mi][nj][h * 2]     + bias_s[warpN * 64 + col];
                o.y = acc[mi][nj][h * 2 + 1] + bias_s[warpN * 64 + col + 1];
                *(float2*)(orow + col) = o;
            }
        }
}

// ---------------- launch ----------------
extern "C" void kernel_launch(void* const* d_in, const int* in_sizes, int n_in,
                              void* d_out, int out_size) {
    const float* x  = (const float*)d_in[0];  // [N, H]
    const float* Wg = (const float*)d_in[1];  // [E, H]
    const float* bg = (const float*)d_in[2];  // [E]
    const float* We = (const float*)d_in[3];  // [E, O, H]
    const float* be = (const float*)d_in[4];  // [E, O]
    float* out = (float*)d_out;               // [N, O]

    int n_tokens = in_sizes[0] / H;

    cudaFuncSetAttribute(expert_gemm, cudaFuncAttributeMaxDynamicSharedMemorySize,
                         SMEM_TOTAL);

    prep_kernel<<<(E * O * H / 4 + 255) / 256, 256>>>(We);
    gate_kernel<<<(n_tokens + 255) / 256, 256>>>(x, Wg, bg, n_tokens);
    scan_kernel<<<1, 32>>>();
    scatter_kernel<<<(n_tokens + 255) / 256, 256>>>(n_tokens);

    dim3 grid(O / BN, MAX_TILES);
    expert_gemm<<<grid, 256, SMEM_TOTAL>>>(be, out);
}

// round 7
// speedup vs baseline: 1.3513x; 1.1704x over previous
#include <cuda_runtime.h>
#include <cuda_fp16.h>
#include <cstdint>

#define H 512
#define O 512
#define E 16
#define N_MAX 32768

#define BM 128          // tokens per CTA tile
#define BN 128          // outputs per CTA tile
#define BKT 64          // fp16 k-elements per smem tile (128B per row)
#define KTILES (H / BKT)
#define MAX_TILES 272

// ---------------- device scratch ----------------
__device__ int g_eidx[N_MAX];
__device__ int g_count[E];
__device__ int g_offset[E];
__device__ int g_cursor[E];
__device__ int g_perm[N_MAX];
__device__ int g_tile_e[MAX_TILES];
__device__ int g_tile_m0[MAX_TILES];
__device__ int g_ntiles;

// pre-split fp16 copies: x = xhi + xlo (22-bit effective), W = whi (11-bit)
__device__ uint16_t g_xhi[N_MAX * H];   // 32 MB
__device__ uint16_t g_xlo[N_MAX * H];   // 32 MB
__device__ uint16_t g_whi[E * O * H];   // 8 MB

// ---------------- helpers ----------------
__device__ __forceinline__ uint32_t smem_u32(const void* p) {
    uint32_t a;
    asm("{ .reg .u64 t; cvta.to.shared.u64 t, %1; cvt.u32.u64 %0, t; }" : "=r"(a) : "l"(p));
    return a;
}
#define SWZ(o) ((o) ^ (((o) >> 3) & 0x70))

__device__ __forceinline__ uint32_t cvt_h2(float a, float b) {
    uint32_t hi;
    asm("cvt.rn.f16x2.f32 %0, %1, %2;" : "=r"(hi) : "f"(b), "f"(a));
    return hi;
}
__device__ __forceinline__ void cvt_split_h(float a, float b, uint32_t& hi, uint32_t& lo) {
    hi = cvt_h2(a, b);
    __half2 h2 = *reinterpret_cast<__half2*>(&hi);
    float2 hf = __half22float2(h2);
    lo = cvt_h2(a - hf.x, b - hf.y);
}

__device__ __forceinline__ void ldsm4(uint32_t* r, uint32_t addr) {
    asm volatile("ldmatrix.sync.aligned.m8n8.x4.shared.b16 {%0,%1,%2,%3}, [%4];"
                 : "=r"(r[0]), "=r"(r[1]), "=r"(r[2]), "=r"(r[3]) : "r"(addr));
}

__device__ __forceinline__ void mma_f16(float* d, const uint32_t* a, const uint32_t* b) {
    asm volatile(
        "mma.sync.aligned.m16n8k16.row.col.f32.f16.f16.f32 "
        "{%0,%1,%2,%3}, {%4,%5,%6,%7}, {%8,%9}, {%0,%1,%2,%3};"
        : "+f"(d[0]), "+f"(d[1]), "+f"(d[2]), "+f"(d[3])
        : "r"(a[0]), "r"(a[1]), "r"(a[2]), "r"(a[3]), "r"(b[0]), "r"(b[1]));
}

__device__ __forceinline__ void cp16(uint32_t dst, const void* src, int srcsz) {
    asm volatile("cp.async.cg.shared.global [%0], [%1], 16, %2;"
                 :: "r"(dst), "l"(src), "r"(srcsz) : "memory");
}
#define CP_COMMIT() asm volatile("cp.async.commit_group;" ::: "memory")
#define CP_WAIT(n)  asm volatile("cp.async.wait_group %0;" :: "n"(n) : "memory")

// ---------------- smem layout (GEMM): 2 stages -> 2 CTAs/SM ----------------
#define STAGE_SZ 49152
#define A_HI 0
#define A_LO 16384
#define B_HI 32768
#define SMEM_TOTAL (1024 + 2 * STAGE_SZ)   // 99328 -> 2 CTAs/SM

// ---------------- stage 0: zero counts + split We -> fp16 hi ----------------
__global__ void prep_kernel(const float* __restrict__ We) {
    int idx = blockIdx.x * blockDim.x + threadIdx.x;
    if (idx < E) g_count[idx] = 0;
    int i = idx * 4;
    if (i < E * O * H) {
        float4 v = *(const float4*)(We + i);
        *(uint2*)(g_whi + i) = make_uint2(cvt_h2(v.x, v.y), cvt_h2(v.z, v.w));
    }
}

// ---------------- stage 1: gate + x split (coalesced, 8 lanes/token) --------
#define GTOK 32   // tokens per block (256 threads / 8 lanes)
__global__ __launch_bounds__(256) void gate_kernel(const float* __restrict__ x,
                                                   const float* __restrict__ Wg,
                                                   const float* __restrict__ bg,
                                                   int n_tokens) {
    __shared__ float Wgs[E * H];  // 32 KB
    int t = threadIdx.x;
    for (int i = t; i < E * H; i += 256) Wgs[i] = Wg[i];
    __syncthreads();

    int lane8 = t & 7;
    int tok = blockIdx.x * GTOK + (t >> 3);
    if (tok >= n_tokens) return;
    const float* xr = x + (size_t)tok * H;

    float acc[E];
#pragma unroll
    for (int e = 0; e < E; e++) acc[e] = 0.f;

#pragma unroll
    for (int i = 0; i < H / 32; i++) {
        int k = i * 32 + lane8 * 4;
        float4 xv = *(const float4*)(xr + k);
        // split + store fp16 hi/lo copies (coalesced: 8 lanes cover 64B/token)
        uint32_t h01, l01, h23, l23;
        cvt_split_h(xv.x, xv.y, h01, l01);
        cvt_split_h(xv.z, xv.w, h23, l23);
        *(uint2*)(g_xhi + (size_t)tok * H + k) = make_uint2(h01, h23);
        *(uint2*)(g_xlo + (size_t)tok * H + k) = make_uint2(l01, l23);
#pragma unroll
        for (int e = 0; e < E; e++) {
            const float* w = &Wgs[e * H + k];
            acc[e] += xv.x * w[0] + xv.y * w[1] + xv.z * w[2] + xv.w * w[3];
        }
    }

    // reduce partial logits across the 8 lanes of this token
#pragma unroll
    for (int e = 0; e < E; e++) {
        acc[e] += __shfl_xor_sync(0xFFFFFFFFu, acc[e], 1);
        acc[e] += __shfl_xor_sync(0xFFFFFFFFu, acc[e], 2);
        acc[e] += __shfl_xor_sync(0xFFFFFFFFu, acc[e], 4);
    }

    if (lane8 == 0) {
#pragma unroll
        for (int e = 0; e < E; e++) acc[e] += bg[e];

        int best = 0;
        float bv = acc[0];
#pragma unroll
        for (int e = 1; e < E; e++)
            if (acc[e] > bv) { bv = acc[e]; best = e; }

        int sec = (best == 0) ? 1 : 0;
        float sv = acc[sec];
#pragma unroll
        for (int e = 0; e < E; e++)
            if (e != best && acc[e] > sv) { sv = acc[e]; sec = e; }

        if (bv - sv < 1e-3f) {  // near-tie: fp64 recompute of both candidates
            int ea = min(best, sec), eb = max(best, sec);
            double la = (double)bg[ea], lb = (double)bg[eb];
            for (int k = 0; k < H; k++) {
                double xv = (double)xr[k];
                la += xv * (double)Wgs[ea * H + k];
                lb += xv * (double)Wgs[eb * H + k];
            }
            best = (lb > la) ? eb : ea;  // first-occurrence tie-break
        }

        g_eidx[tok] = best;
        atomicAdd(&g_count[best], 1);
    }
}

// ---------------- stage 2: warp-parallel scan + tile table ----------------
__global__ void scan_kernel() {
    int lane = threadIdx.x;
    int c = (lane < E) ? g_count[lane] : 0;
    int nt = (c + BM - 1) / BM;
    int sc = c, snt = nt;
#pragma unroll
    for (int d = 1; d < 32; d <<= 1) {
        int vc = __shfl_up_sync(0xFFFFFFFFu, sc, d);
        int vn = __shfl_up_sync(0xFFFFFFFFu, snt, d);
        if (lane >= d) { sc += vc; snt += vn; }
    }
    int off = sc - c;
    int toff = snt - nt;
    if (lane < E) {
        g_offset[lane] = off;
        g_cursor[lane] = off;
        for (int i = 0; i < nt; i++) {
            g_tile_e[toff + i] = lane;
            g_tile_m0[toff + i] = i * BM;
        }
    }
    if (lane == 31) g_ntiles = snt;
}

// ---------------- stage 3: scatter ----------------
__global__ void scatter_kernel(int n_tokens) {
    int n = blockIdx.x * blockDim.x + threadIdx.x;
    if (n >= n_tokens) return;
    int e = g_eidx[n];
    int slot = atomicAdd(&g_cursor[e], 1);
    g_perm[slot] = n;
}

// ---------------- stage 4: HMMA gather-GEMM, 2-stage, 2 CTAs/SM ------------
__global__ __launch_bounds__(256, 2) void expert_gemm(const float* __restrict__ be,
                                                      float* __restrict__ out) {
    int tile = blockIdx.y;
    if (tile >= g_ntiles) return;
    int t = threadIdx.x;
    int e = g_tile_e[tile];
    int m0 = g_tile_m0[tile];
    int cnt = g_count[e];
    int base = g_offset[e];
    int n0 = blockIdx.x * BN;

    extern __shared__ char smem[];
    int* rows = (int*)smem;
    float* bias_s = (float*)(smem + 512);
    uint32_t sb = smem_u32(smem);

    if (t < BM) {
        int m = m0 + t;
        rows[t] = (m < cnt) ? g_perm[base + m] : -1;
        bias_s[t] = be[e * O + n0 + t];
    }
    __syncthreads();

    // ---- loader: thread t owns chunks c = t + g*256, g<4; row=c>>3, ch=c&7 ----
    uint32_t offA[4];   // 32-bit elem offsets into g_xhi / g_xlo
    uint32_t offB[4];   // 32-bit elem offsets into g_whi
    int szA[4];
    uint32_t dsw[4];
#pragma unroll
    for (int g = 0; g < 4; g++) {
        int c = t + g * 256;
        int row = c >> 3, ch = c & 7;
        int r = rows[row];
        szA[g] = (r >= 0) ? 16 : 0;
        offA[g] = (uint32_t)(r < 0 ? 0 : r) * H + ch * 8;
        offB[g] = (uint32_t)(e * O + n0 + row) * H + ch * 8;
        dsw[g] = SWZ((uint32_t)(row * 128 + ch * 16));
    }

#define ISSUE_TILE(kt, bufbase)                                              \
    {                                                                        \
        int koff = (kt) * BKT;                                               \
        _Pragma("unroll") for (int g = 0; g < 4; g++) {                      \
            cp16((bufbase) + A_HI + dsw[g], g_xhi + offA[g] + koff, szA[g]); \
            cp16((bufbase) + A_LO + dsw[g], g_xlo + offA[g] + koff, szA[g]); \
            cp16((bufbase) + B_HI + dsw[g], g_whi + offB[g] + koff, 16);     \
        }                                                                    \
        CP_COMMIT();                                                         \
    }

    // ---- warp tiling: 8 warps = 4m x 2n, warp tile 32x64 ----
    int w = t >> 5, lane = t & 31;
    int warpM = w & 3, warpN = w >> 2;
    int grp = lane >> 3, lr = lane & 7;
    int arow = lr + (grp & 1) * 8;
    int akc = (grp >> 1) * 8;
    int brow = (grp >> 1) * 8 + lr;
    int bkc = (grp & 1) * 8;

    float acc[2][8][4];
#pragma unroll
    for (int i = 0; i < 2; i++)
#pragma unroll
        for (int j = 0; j < 8; j++)
#pragma unroll
            for (int c = 0; c < 4; c++) acc[i][j][c] = 0.f;

    uint32_t buf0 = sb + 1024, buf1 = sb + 1024 + STAGE_SZ;

    ISSUE_TILE(0, buf0);
    ISSUE_TILE(1, buf1);

    for (int kt = 0; kt < KTILES; kt++) {
        uint32_t bufb = (kt & 1) ? buf1 : buf0;
        if (kt == KTILES - 1) { CP_WAIT(0); } else { CP_WAIT(1); }
        __syncthreads();  // tile kt visible to all

#pragma unroll
        for (int ks = 0; ks < 4; ks++) {
            uint32_t ah[2][4], al[2][4], bh[4][4];
            uint32_t aoff[2];
#pragma unroll
            for (int mi = 0; mi < 2; mi++) {
                aoff[mi] = SWZ((uint32_t)((warpM * 32 + mi * 16 + arow) * 128 +
                                          (ks * 16 + akc) * 2));
                ldsm4(ah[mi], bufb + A_HI + aoff[mi]);
            }
#pragma unroll
            for (int njp = 0; njp < 4; njp++) {
                uint32_t off = SWZ((uint32_t)((warpN * 64 + njp * 16 + brow) * 128 +
                                              (ks * 16 + bkc) * 2));
                ldsm4(bh[njp], bufb + B_HI + off);
            }
            // phase 1: all hi-term MMAs (16 distinct accs -> no back-to-back dep)
#pragma unroll
            for (int mi = 0; mi < 2; mi++)
#pragma unroll
                for (int njp = 0; njp < 4; njp++) {
                    mma_f16(acc[mi][njp * 2],     ah[mi], &bh[njp][0]);
                    mma_f16(acc[mi][njp * 2 + 1], ah[mi], &bh[njp][2]);
                }
            // load lo fragments between phases (keeps live set down)
#pragma unroll
            for (int mi = 0; mi < 2; mi++) ldsm4(al[mi], bufb + A_LO + aoff[mi]);
            // phase 2: all lo-term MMAs
#pragma unroll
            for (int mi = 0; mi < 2; mi++)
#pragma unroll
                for (int njp = 0; njp < 4; njp++) {
                    mma_f16(acc[mi][njp * 2],     al[mi], &bh[njp][0]);
                    mma_f16(acc[mi][njp * 2 + 1], al[mi], &bh[njp][2]);
                }
        }
        __syncthreads();  // all reads of buf kt done
        if (kt + 2 < KTILES) ISSUE_TILE(kt + 2, bufb);
    }

    // ---- epilogue: acc + bias -> gathered token rows ----
    int qrow = lane >> 2, qcol = lane & 3;
#pragma unroll
    for (int mi = 0; mi < 2; mi++)
#pragma unroll
        for (int h = 0; h < 2; h++) {
            int m = warpM * 32 + mi * 16 + h * 8 + qrow;
            int r = rows[m];
            if (r < 0) continue;
            float* orow = out + (size_t)r * O + n0 + warpN * 64;
#pragma unroll
            for (int nj = 0; nj < 8; nj++) {
                int col = nj * 8 + qcol * 2;
                float2 o;
                o.x = acc[mi][nj][h * 2]     + bias_s[warpN * 64 + col];
                o.y = acc[mi][nj][h * 2 + 1] + bias_s[warpN * 64 + col + 1];
                *(float2*)(orow + col) = o;
            }
        }
}

// ---------------- launch ----------------
extern "C" void kernel_launch(void* const* d_in, const int* in_sizes, int n_in,
                              void* d_out, int out_size) {
    const float* x  = (const float*)d_in[0];  // [N, H]
    const float* Wg = (const float*)d_in[1];  // [E, H]
    const float* bg = (const float*)d_in[2];  // [E]
    const float* We = (const float*)d_in[3];  // [E, O, H]
    const float* be = (const float*)d_in[4];  // [E, O]
    float* out = (float*)d_out;               // [N, O]

    int n_tokens = in_sizes[0] / H;

    cudaFuncSetAttribute(expert_gemm, cudaFuncAttributeMaxDynamicSharedMemorySize,
                         SMEM_TOTAL);

    prep_kernel<<<(E * O * H / 4 + 255) / 256, 256>>>(We);
    gate_kernel<<<(n_tokens + GTOK - 1) / GTOK, 256>>>(x, Wg, bg, n_tokens);
    scan_kernel<<<1, 32>>>();
    scatter_kernel<<<(n_tokens + 255) / 256, 256>>>(n_tokens);

    dim3 grid(O / BN, MAX_TILES);
    expert_gemm<<<grid, 256, SMEM_TOTAL>>>(be, out);
}

// round 8
// speedup vs baseline: 1.6759x; 1.2402x over previous
#include <cuda_runtime.h>
#include <cuda_fp16.h>
#include <cstdint>

#define H 512
#define O 512
#define E 16
#define N_MAX 32768

#define BM 128          // tokens per CTA tile
#define BN 128          // outputs per CTA tile
#define BKT 64          // fp16 k-elements per smem tile (128B per row)
#define KTILES (H / BKT)
#define MAX_TILES 272

// ---------------- device scratch ----------------
__device__ int g_eidx[N_MAX];
__device__ int g_slot[N_MAX];
__device__ int g_count[E];
__device__ int g_offset[E];
__device__ int g_perm[N_MAX];
__device__ int g_tile_e[MAX_TILES];
__device__ int g_tile_m0[MAX_TILES];
__device__ int g_ntiles;

// pre-converted fp16 copies
__device__ uint16_t g_xhi[N_MAX * H];   // 32 MB
__device__ uint16_t g_whi[E * O * H];   // 8 MB

// ---------------- helpers ----------------
__device__ __forceinline__ uint32_t smem_u32(const void* p) {
    uint32_t a;
    asm("{ .reg .u64 t; cvta.to.shared.u64 t, %1; cvt.u32.u64 %0, t; }" : "=r"(a) : "l"(p));
    return a;
}
#define SWZ(o) ((o) ^ (((o) >> 3) & 0x70))

__device__ __forceinline__ uint32_t cvt_h2(float a, float b) {
    uint32_t hi;
    asm("cvt.rn.f16x2.f32 %0, %1, %2;" : "=r"(hi) : "f"(b), "f"(a));
    return hi;
}

__device__ __forceinline__ void ldsm4(uint32_t* r, uint32_t addr) {
    asm volatile("ldmatrix.sync.aligned.m8n8.x4.shared.b16 {%0,%1,%2,%3}, [%4];"
                 : "=r"(r[0]), "=r"(r[1]), "=r"(r[2]), "=r"(r[3]) : "r"(addr));
}

__device__ __forceinline__ void mma_f16(float* d, const uint32_t* a, const uint32_t* b) {
    asm volatile(
        "mma.sync.aligned.m16n8k16.row.col.f32.f16.f16.f32 "
        "{%0,%1,%2,%3}, {%4,%5,%6,%7}, {%8,%9}, {%0,%1,%2,%3};"
        : "+f"(d[0]), "+f"(d[1]), "+f"(d[2]), "+f"(d[3])
        : "r"(a[0]), "r"(a[1]), "r"(a[2]), "r"(a[3]), "r"(b[0]), "r"(b[1]));
}

__device__ __forceinline__ void cp16(uint32_t dst, const void* src, int srcsz) {
    asm volatile("cp.async.cg.shared.global [%0], [%1], 16, %2;"
                 :: "r"(dst), "l"(src), "r"(srcsz) : "memory");
}
#define CP_COMMIT() asm volatile("cp.async.commit_group;" ::: "memory")
#define CP_WAIT(n)  asm volatile("cp.async.wait_group %0;" :: "n"(n) : "memory")

// ---------------- smem layout (GEMM): 3 stages x 32KB -> 2 CTAs/SM ----------
#define STAGE_SZ 32768
#define A_HI 0
#define B_HI 16384
#define SMEM_TOTAL (1024 + 3 * STAGE_SZ)   // 99328 -> 2 CTAs/SM

// ---------------- stage 0: zero counts + convert We -> fp16 ----------------
__global__ void prep_kernel(const float* __restrict__ We) {
    int idx = blockIdx.x * blockDim.x + threadIdx.x;
    if (idx < E) g_count[idx] = 0;
    int i = idx * 4;
    if (i < E * O * H) {
        float4 v = *(const float4*)(We + i);
        *(uint2*)(g_whi + i) = make_uint2(cvt_h2(v.x, v.y), cvt_h2(v.z, v.w));
    }
}

// ---------------- stage 1: gate + x convert (coalesced, 8 lanes/token) ------
#define GTOK 32   // tokens per block (256 threads / 8 lanes)
__global__ __launch_bounds__(256) void gate_kernel(const float* __restrict__ x,
                                                   const float* __restrict__ Wg,
                                                   const float* __restrict__ bg,
                                                   int n_tokens) {
    __shared__ float Wgs[E * H];  // 32 KB
    int t = threadIdx.x;
    for (int i = t; i < E * H; i += 256) Wgs[i] = Wg[i];
    __syncthreads();

    int lane8 = t & 7;
    int tok = blockIdx.x * GTOK + (t >> 3);
    if (tok >= n_tokens) return;
    const float* xr = x + (size_t)tok * H;

    float acc[E];
#pragma unroll
    for (int e = 0; e < E; e++) acc[e] = 0.f;

#pragma unroll
    for (int i = 0; i < H / 32; i++) {
        int k = i * 32 + lane8 * 4;
        float4 xv = *(const float4*)(xr + k);
        *(uint2*)(g_xhi + (size_t)tok * H + k) =
            make_uint2(cvt_h2(xv.x, xv.y), cvt_h2(xv.z, xv.w));
#pragma unroll
        for (int e = 0; e < E; e++) {
            const float* w = &Wgs[e * H + k];
            acc[e] += xv.x * w[0] + xv.y * w[1] + xv.z * w[2] + xv.w * w[3];
        }
    }

    // reduce partial logits across the 8 lanes of this token
#pragma unroll
    for (int e = 0; e < E; e++) {
        acc[e] += __shfl_xor_sync(0xFFFFFFFFu, acc[e], 1);
        acc[e] += __shfl_xor_sync(0xFFFFFFFFu, acc[e], 2);
        acc[e] += __shfl_xor_sync(0xFFFFFFFFu, acc[e], 4);
    }

    if (lane8 == 0) {
#pragma unroll
        for (int e = 0; e < E; e++) acc[e] += bg[e];

        int best = 0;
        float bv = acc[0];
#pragma unroll
        for (int e = 1; e < E; e++)
            if (acc[e] > bv) { bv = acc[e]; best = e; }

        int sec = (best == 0) ? 1 : 0;
        float sv = acc[sec];
#pragma unroll
        for (int e = 0; e < E; e++)
            if (e != best && acc[e] > sv) { sv = acc[e]; sec = e; }

        if (bv - sv < 1e-3f) {  // near-tie: fp64 recompute of both candidates
            int ea = min(best, sec), eb = max(best, sec);
            double la = (double)bg[ea], lb = (double)bg[eb];
            for (int k = 0; k < H; k++) {
                double xv = (double)xr[k];
                la += xv * (double)Wgs[ea * H + k];
                lb += xv * (double)Wgs[eb * H + k];
            }
            best = (lb > la) ? eb : ea;  // first-occurrence tie-break
        }

        g_eidx[tok] = best;
        g_slot[tok] = atomicAdd(&g_count[best], 1);  // slot within expert
    }
}

// ---------------- stage 2: warp-parallel scan + tile table ----------------
__global__ void scan_kernel() {
    int lane = threadIdx.x;
    int c = (lane < E) ? g_count[lane] : 0;
    int nt = (c + BM - 1) / BM;
    int sc = c, snt = nt;
#pragma unroll
    for (int d = 1; d < 32; d <<= 1) {
        int vc = __shfl_up_sync(0xFFFFFFFFu, sc, d);
        int vn = __shfl_up_sync(0xFFFFFFFFu, snt, d);
        if (lane >= d) { sc += vc; snt += vn; }
    }
    int off = sc - c;
    int toff = snt - nt;
    if (lane < E) {
        g_offset[lane] = off;
        for (int i = 0; i < nt; i++) {
            g_tile_e[toff + i] = lane;
            g_tile_m0[toff + i] = i * BM;
        }
    }
    if (lane == 31) g_ntiles = snt;
}

// ---------------- stage 3: scatter (no atomics) ----------------
__global__ void scatter_kernel(int n_tokens) {
    int n = blockIdx.x * blockDim.x + threadIdx.x;
    if (n >= n_tokens) return;
    g_perm[g_offset[g_eidx[n]] + g_slot[n]] = n;
}

// ---------------- stage 4: fp16 HMMA gather-GEMM, 3-stage, 2 CTAs/SM --------
__global__ __launch_bounds__(256, 2) void expert_gemm(const float* __restrict__ be,
                                                      float* __restrict__ out) {
    int tile = blockIdx.y;
    if (tile >= g_ntiles) return;
    int t = threadIdx.x;
    int e = g_tile_e[tile];
    int m0 = g_tile_m0[tile];
    int cnt = g_count[e];
    int base = g_offset[e];
    int n0 = blockIdx.x * BN;

    extern __shared__ char smem[];
    int* rows = (int*)smem;
    float* bias_s = (float*)(smem + 512);
    uint32_t sb = smem_u32(smem);

    if (t < BM) {
        int m = m0 + t;
        rows[t] = (m < cnt) ? g_perm[base + m] : -1;
        bias_s[t] = be[e * O + n0 + t];
    }
    __syncthreads();

    // ---- loader: thread t owns chunks c = t + g*256, g<4; row=c>>3, ch=c&7 ----
    uint32_t offA[4];
    uint32_t offB[4];
    int szA[4];
    uint32_t dsw[4];
#pragma unroll
    for (int g = 0; g < 4; g++) {
        int c = t + g * 256;
        int row = c >> 3, ch = c & 7;
        int r = rows[row];
        szA[g] = (r >= 0) ? 16 : 0;
        offA[g] = (uint32_t)(r < 0 ? 0 : r) * H + ch * 8;
        offB[g] = (uint32_t)(e * O + n0 + row) * H + ch * 8;
        dsw[g] = SWZ((uint32_t)(row * 128 + ch * 16));
    }

#define ISSUE_TILE(kt, bufbase)                                              \
    {                                                                        \
        int koff = (kt) * BKT;                                               \
        _Pragma("unroll") for (int g = 0; g < 4; g++) {                      \
            cp16((bufbase) + A_HI + dsw[g], g_xhi + offA[g] + koff, szA[g]); \
            cp16((bufbase) + B_HI + dsw[g], g_whi + offB[g] + koff, 16);     \
        }                                                                    \
        CP_COMMIT();                                                         \
    }

    // ---- warp tiling: 8 warps = 4m x 2n, warp tile 32x64 ----
    int w = t >> 5, lane = t & 31;
    int warpM = w & 3, warpN = w >> 2;
    int grp = lane >> 3, lr = lane & 7;
    int arow = lr + (grp & 1) * 8;
    int akc = (grp >> 1) * 8;
    int brow = (grp >> 1) * 8 + lr;
    int bkc = (grp & 1) * 8;

    float acc[2][8][4];
#pragma unroll
    for (int i = 0; i < 2; i++)
#pragma unroll
        for (int j = 0; j < 8; j++)
#pragma unroll
            for (int c = 0; c < 4; c++) acc[i][j][c] = 0.f;

    uint32_t bufs[3] = {sb + 1024, sb + 1024 + STAGE_SZ, sb + 1024 + 2 * STAGE_SZ};

    ISSUE_TILE(0, bufs[0]);
    ISSUE_TILE(1, bufs[1]);
    ISSUE_TILE(2, bufs[2]);

    for (int kt = 0; kt < KTILES; kt++) {
        // exact wait: groups issued after kt = min(kt+2, KTILES-1) - kt
        if (kt < KTILES - 2)      { CP_WAIT(2); }
        else if (kt == KTILES - 2){ CP_WAIT(1); }
        else                      { CP_WAIT(0); }
        __syncthreads();  // tile kt visible; prior reads of this buf done

        uint32_t bufb = bufs[kt % 3];
#pragma unroll
        for (int ks = 0; ks < 4; ks++) {
            uint32_t ah[2][4], bh[4][4];
#pragma unroll
            for (int mi = 0; mi < 2; mi++) {
                uint32_t off = SWZ((uint32_t)((warpM * 32 + mi * 16 + arow) * 128 +
                                              (ks * 16 + akc) * 2));
                ldsm4(ah[mi], bufb + A_HI + off);
            }
#pragma unroll
            for (int njp = 0; njp < 4; njp++) {
                uint32_t off = SWZ((uint32_t)((warpN * 64 + njp * 16 + brow) * 128 +
                                              (ks * 16 + bkc) * 2));
                ldsm4(bh[njp], bufb + B_HI + off);
            }
#pragma unroll
            for (int mi = 0; mi < 2; mi++)
#pragma unroll
                for (int njp = 0; njp < 4; njp++) {
                    mma_f16(acc[mi][njp * 2],     ah[mi], &bh[njp][0]);
                    mma_f16(acc[mi][njp * 2 + 1], ah[mi], &bh[njp][2]);
                }
        }
        __syncthreads();  // all reads of buf kt done before refill below
        if (kt + 3 < KTILES) ISSUE_TILE(kt + 3, bufs[(kt + 3) % 3]);
    }

    // ---- epilogue: acc + bias -> gathered token rows ----
    int qrow = lane >> 2, qcol = lane & 3;
#pragma unroll
    for (int mi = 0; mi < 2; mi++)
#pragma unroll
        for (int h = 0; h < 2; h++) {
            int m = warpM * 32 + mi * 16 + h * 8 + qrow;
            int r = rows[m];
            if (r < 0) continue;
            float* orow = out + (size_t)r * O + n0 + warpN * 64;
#pragma unroll
            for (int nj = 0; nj < 8; nj++) {
                int col = nj * 8 + qcol * 2;
                float2 o;
                o.x = acc[mi][nj][h * 2]     + bias_s[warpN * 64 + col];
                o.y = acc[mi][nj][h * 2 + 1] + bias_s[warpN * 64 + col + 1];
                *(float2*)(orow + col) = o;
            }
        }
}

// ---------------- launch ----------------
extern "C" void kernel_launch(void* const* d_in, const int* in_sizes, int n_in,
                              void* d_out, int out_size) {
    const float* x  = (const float*)d_in[0];  // [N, H]
    const float* Wg = (const float*)d_in[1];  // [E, H]
    const float* bg = (const float*)d_in[2];  // [E]
    const float* We = (const float*)d_in[3];  // [E, O, H]
    const float* be = (const float*)d_in[4];  // [E, O]
    float* out = (float*)d_out;               // [N, O]

    int n_tokens = in_sizes[0] / H;

    cudaFuncSetAttribute(expert_gemm, cudaFuncAttributeMaxDynamicSharedMemorySize,
                         SMEM_TOTAL);

    prep_kernel<<<(E * O * H / 4 + 255) / 256, 256>>>(We);
    gate_kernel<<<(n_tokens + GTOK - 1) / GTOK, 256>>>(x, Wg, bg, n_tokens);
    scan_kernel<<<1, 32>>>();
    scatter_kernel<<<(n_tokens + 255) / 256, 256>>>(n_tokens);

    dim3 grid(O / BN, MAX_TILES);
    expert_gemm<<<grid, 256, SMEM_TOTAL>>>(be, out);
}

// round 9
// speedup vs baseline: 1.7870x; 1.0663x over previous
#include <cuda_runtime.h>
#include <cuda_fp16.h>
#include <cstdint>

#define H 512
#define O 512
#define E 16
#define N_MAX 32768

#define BM 128          // tokens per CTA tile
#define BN 128          // outputs per CTA tile
#define BKT 64          // fp16 k-elements per smem tile (128B per row)
#define KTILES (H / BKT)
#define MAX_TILES 272

// ---------------- device scratch ----------------
__device__ int g_eidx[N_MAX];
__device__ int g_slot[N_MAX];
__device__ int g_count[E];    // zeroed at start (static) and re-zeroed by scan each run
__device__ int g_ecnt[E];
__device__ int g_offset[E];
__device__ int g_perm[N_MAX];
__device__ int g_tile_e[MAX_TILES];
__device__ int g_tile_m0[MAX_TILES];
__device__ int g_ntiles;

// pre-converted fp16 copies
__device__ uint16_t g_xhi[N_MAX * H];   // 32 MB
__device__ uint16_t g_whi[E * O * H];   // 8 MB

// ---------------- helpers ----------------
__device__ __forceinline__ uint32_t smem_u32(const void* p) {
    uint32_t a;
    asm("{ .reg .u64 t; cvta.to.shared.u64 t, %1; cvt.u32.u64 %0, t; }" : "=r"(a) : "l"(p));
    return a;
}
#define SWZ(o) ((o) ^ (((o) >> 3) & 0x70))

__device__ __forceinline__ uint32_t cvt_h2(float a, float b) {
    uint32_t hi;
    asm("cvt.rn.f16x2.f32 %0, %1, %2;" : "=r"(hi) : "f"(b), "f"(a));
    return hi;
}

__device__ __forceinline__ void ldsm4(uint32_t* r, uint32_t addr) {
    asm volatile("ldmatrix.sync.aligned.m8n8.x4.shared.b16 {%0,%1,%2,%3}, [%4];"
                 : "=r"(r[0]), "=r"(r[1]), "=r"(r[2]), "=r"(r[3]) : "r"(addr));
}

__device__ __forceinline__ void mma_f16(float* d, const uint32_t* a, const uint32_t* b) {
    asm volatile(
        "mma.sync.aligned.m16n8k16.row.col.f32.f16.f16.f32 "
        "{%0,%1,%2,%3}, {%4,%5,%6,%7}, {%8,%9}, {%0,%1,%2,%3};"
        : "+f"(d[0]), "+f"(d[1]), "+f"(d[2]), "+f"(d[3])
        : "r"(a[0]), "r"(a[1]), "r"(a[2]), "r"(a[3]), "r"(b[0]), "r"(b[1]));
}

__device__ __forceinline__ void cp16(uint32_t dst, const void* src, int srcsz) {
    asm volatile("cp.async.cg.shared.global [%0], [%1], 16, %2;"
                 :: "r"(dst), "l"(src), "r"(srcsz) : "memory");
}
#define CP_COMMIT() asm volatile("cp.async.commit_group;" ::: "memory")
#define CP_WAIT(n)  asm volatile("cp.async.wait_group %0;" :: "n"(n) : "memory")

// ---------------- smem layout (GEMM): 3 stages x 32KB -> 2 CTAs/SM ----------
#define STAGE_SZ 32768
#define A_HI 0
#define B_HI 16384
#define SMEM_TOTAL (1024 + 3 * STAGE_SZ)   // 99328 -> 2 CTAs/SM
#define EPI_STRIDE 132                      // padded fp32 row stride for epilogue staging

// ---------------- stage 1: gate + x convert + fused We convert --------------
#define GTOK 32   // tokens per block (256 threads / 8 lanes)
__global__ __launch_bounds__(256) void gate_kernel(const float* __restrict__ x,
                                                   const float* __restrict__ Wg,
                                                   const float* __restrict__ bg,
                                                   const float* __restrict__ We,
                                                   int n_tokens) {
    __shared__ float Wgs[E * H];  // 32 KB
    int t = threadIdx.x;

    // fused We -> fp16 conversion (grid-stride over 4-elem chunks)
    for (int c = blockIdx.x * 256 + t; c < E * O * H / 4; c += gridDim.x * 256) {
        int i = c * 4;
        float4 v = *(const float4*)(We + i);
        *(uint2*)(g_whi + i) = make_uint2(cvt_h2(v.x, v.y), cvt_h2(v.z, v.w));
    }

    for (int i = t; i < E * H; i += 256) Wgs[i] = Wg[i];
    __syncthreads();

    int lane8 = t & 7;
    int tok = blockIdx.x * GTOK + (t >> 3);
    if (tok >= n_tokens) return;
    const float* xr = x + (size_t)tok * H;

    float acc[E];
#pragma unroll
    for (int e = 0; e < E; e++) acc[e] = 0.f;

#pragma unroll
    for (int i = 0; i < H / 32; i++) {
        int k = i * 32 + lane8 * 4;
        float4 xv = *(const float4*)(xr + k);
        *(uint2*)(g_xhi + (size_t)tok * H + k) =
            make_uint2(cvt_h2(xv.x, xv.y), cvt_h2(xv.z, xv.w));
#pragma unroll
        for (int e = 0; e < E; e++) {
            const float* w = &Wgs[e * H + k];
            acc[e] += xv.x * w[0] + xv.y * w[1] + xv.z * w[2] + xv.w * w[3];
        }
    }

    // reduce partial logits across the 8 lanes of this token
#pragma unroll
    for (int e = 0; e < E; e++) {
        acc[e] += __shfl_xor_sync(0xFFFFFFFFu, acc[e], 1);
        acc[e] += __shfl_xor_sync(0xFFFFFFFFu, acc[e], 2);
        acc[e] += __shfl_xor_sync(0xFFFFFFFFu, acc[e], 4);
    }

    if (lane8 == 0) {
#pragma unroll
        for (int e = 0; e < E; e++) acc[e] += bg[e];

        int best = 0;
        float bv = acc[0];
#pragma unroll
        for (int e = 1; e < E; e++)
            if (acc[e] > bv) { bv = acc[e]; best = e; }

        int sec = (best == 0) ? 1 : 0;
        float sv = acc[sec];
#pragma unroll
        for (int e = 0; e < E; e++)
            if (e != best && acc[e] > sv) { sv = acc[e]; sec = e; }

        if (bv - sv < 1e-3f) {  // near-tie: fp64 recompute of both candidates
            int ea = min(best, sec), eb = max(best, sec);
            double la = (double)bg[ea], lb = (double)bg[eb];
            for (int k = 0; k < H; k++) {
                double xv = (double)xr[k];
                la += xv * (double)Wgs[ea * H + k];
                lb += xv * (double)Wgs[eb * H + k];
            }
            best = (lb > la) ? eb : ea;  // first-occurrence tie-break
        }

        g_eidx[tok] = best;
        g_slot[tok] = atomicAdd(&g_count[best], 1);  // slot within expert
    }
}

// ---------------- stage 2: scan + tile table; self-cleans g_count ----------
__global__ void scan_kernel() {
    int lane = threadIdx.x;
    int c = (lane < E) ? g_count[lane] : 0;
    int nt = (c + BM - 1) / BM;
    int sc = c, snt = nt;
#pragma unroll
    for (int d = 1; d < 32; d <<= 1) {
        int vc = __shfl_up_sync(0xFFFFFFFFu, sc, d);
        int vn = __shfl_up_sync(0xFFFFFFFFu, snt, d);
        if (lane >= d) { sc += vc; snt += vn; }
    }
    int off = sc - c;
    int toff = snt - nt;
    if (lane < E) {
        g_offset[lane] = off;
        g_ecnt[lane] = c;
        g_count[lane] = 0;  // restore invariant for next invocation
        for (int i = 0; i < nt; i++) {
            g_tile_e[toff + i] = lane;
            g_tile_m0[toff + i] = i * BM;
        }
    }
    if (lane == 31) g_ntiles = snt;
}

// ---------------- stage 3: scatter (no atomics) ----------------
__global__ void scatter_kernel(int n_tokens) {
    int n = blockIdx.x * blockDim.x + threadIdx.x;
    if (n >= n_tokens) return;
    g_perm[g_offset[g_eidx[n]] + g_slot[n]] = n;
}

// ---------------- stage 4: fp16 HMMA gather-GEMM ----------------
__global__ __launch_bounds__(256, 2) void expert_gemm(const float* __restrict__ be,
                                                      float* __restrict__ out) {
    int tile = blockIdx.y;
    if (tile >= g_ntiles) return;
    int t = threadIdx.x;
    int e = g_tile_e[tile];
    int m0 = g_tile_m0[tile];
    int cnt = g_ecnt[e];
    int base = g_offset[e];
    int n0 = blockIdx.x * BN;

    extern __shared__ char smem[];
    int* rows = (int*)smem;
    float* bias_s = (float*)(smem + 512);
    float* stage = (float*)(smem + 1024);   // epilogue staging (aliases k-stages)
    uint32_t sb = smem_u32(smem);

    if (t < BM) {
        int m = m0 + t;
        rows[t] = (m < cnt) ? g_perm[base + m] : -1;
        bias_s[t] = be[e * O + n0 + t];
    }
    __syncthreads();

    // ---- loader: thread t owns chunks c = t + g*256, g<4; row=c>>3, ch=c&7 ----
    uint32_t offA[4];
    uint32_t offB[4];
    int szA[4];
    uint32_t dsw[4];
#pragma unroll
    for (int g = 0; g < 4; g++) {
        int c = t + g * 256;
        int row = c >> 3, ch = c & 7;
        int r = rows[row];
        szA[g] = (r >= 0) ? 16 : 0;
        offA[g] = (uint32_t)(r < 0 ? 0 : r) * H + ch * 8;
        offB[g] = (uint32_t)(e * O + n0 + row) * H + ch * 8;
        dsw[g] = SWZ((uint32_t)(row * 128 + ch * 16));
    }

#define ISSUE_TILE(kt, bufbase)                                              \
    {                                                                        \
        int koff = (kt) * BKT;                                               \
        _Pragma("unroll") for (int g = 0; g < 4; g++) {                      \
            cp16((bufbase) + A_HI + dsw[g], g_xhi + offA[g] + koff, szA[g]); \
            cp16((bufbase) + B_HI + dsw[g], g_whi + offB[g] + koff, 16);     \
        }                                                                    \
        CP_COMMIT();                                                         \
    }

    // ---- warp tiling: 8 warps = 4m x 2n, warp tile 32x64 ----
    int w = t >> 5, lane = t & 31;
    int warpM = w & 3, warpN = w >> 2;
    int grp = lane >> 3, lr = lane & 7;
    int arow = lr + (grp & 1) * 8;
    int akc = (grp >> 1) * 8;
    int brow = (grp >> 1) * 8 + lr;
    int bkc = (grp & 1) * 8;

    float acc[2][8][4];
#pragma unroll
    for (int i = 0; i < 2; i++)
#pragma unroll
        for (int j = 0; j < 8; j++)
#pragma unroll
            for (int c = 0; c < 4; c++) acc[i][j][c] = 0.f;

    uint32_t bufs[3] = {sb + 1024, sb + 1024 + STAGE_SZ, sb + 1024 + 2 * STAGE_SZ};

    ISSUE_TILE(0, bufs[0]);
    ISSUE_TILE(1, bufs[1]);

    for (int kt = 0; kt < KTILES; kt++) {
        // groups issued so far: 0..min(kt+1, KTILES-1). wait(1) -> group kt done.
        if (kt < KTILES - 1) { CP_WAIT(1); } else { CP_WAIT(0); }
        __syncthreads();  // tile kt visible; reads of bufs[(kt+2)%3] (iter kt-1) done
        if (kt + 2 < KTILES) ISSUE_TILE(kt + 2, bufs[(kt + 2) % 3]);

        uint32_t bufb = bufs[kt % 3];
#pragma unroll
        for (int ks = 0; ks < 4; ks++) {
            uint32_t ah[2][4], bh[4][4];
#pragma unroll
            for (int mi = 0; mi < 2; mi++) {
                uint32_t off = SWZ((uint32_t)((warpM * 32 + mi * 16 + arow) * 128 +
                                              (ks * 16 + akc) * 2));
                ldsm4(ah[mi], bufb + A_HI + off);
            }
#pragma unroll
            for (int njp = 0; njp < 4; njp++) {
                uint32_t off = SWZ((uint32_t)((warpN * 64 + njp * 16 + brow) * 128 +
                                              (ks * 16 + bkc) * 2));
                ldsm4(bh[njp], bufb + B_HI + off);
            }
#pragma unroll
            for (int mi = 0; mi < 2; mi++)
#pragma unroll
                for (int njp = 0; njp < 4; njp++) {
                    mma_f16(acc[mi][njp * 2],     ah[mi], &bh[njp][0]);
                    mma_f16(acc[mi][njp * 2 + 1], ah[mi], &bh[njp][2]);
                }
        }
    }

    // ---- epilogue: fragments -> smem stage -> coalesced float4 stores ------
    __syncthreads();  // all warps done reading k-stage smem
    int qrow = lane >> 2, qcol = lane & 3;
#pragma unroll
    for (int mi = 0; mi < 2; mi++)
#pragma unroll
        for (int h = 0; h < 2; h++) {
            int m = warpM * 32 + mi * 16 + h * 8 + qrow;
            float* srow = stage + m * EPI_STRIDE + warpN * 64;
#pragma unroll
            for (int nj = 0; nj < 8; nj++) {
                int col = nj * 8 + qcol * 2;
                srow[col]     = acc[mi][nj][h * 2];
                srow[col + 1] = acc[mi][nj][h * 2 + 1];
            }
        }
    __syncthreads();

#pragma unroll
    for (int i = 0; i < 16; i++) {
        int idx = t + i * 256;
        int row = idx >> 5, c4 = idx & 31;
        int r = rows[row];
        if (r < 0) continue;
        const float* srow = stage + row * EPI_STRIDE + c4 * 4;
        float4 bv = *(const float4*)(bias_s + c4 * 4);
        float4 o;
        o.x = srow[0] + bv.x;
        o.y = srow[1] + bv.y;
        o.z = srow[2] + bv.z;
        o.w = srow[3] + bv.w;
        *(float4*)(out + (size_t)r * O + n0 + c4 * 4) = o;
    }
}

// ---------------- launch ----------------
extern "C" void kernel_launch(void* const* d_in, const int* in_sizes, int n_in,
                              void* d_out, int out_size) {
    const float* x  = (const float*)d_in[0];  // [N, H]
    const float* Wg = (const float*)d_in[1];  // [E, H]
    const float* bg = (const float*)d_in[2];  // [E]
    const float* We = (const float*)d_in[3];  // [E, O, H]
    const float* be = (const float*)d_in[4];  // [E, O]
    float* out = (float*)d_out;               // [N, O]

    int n_tokens = in_sizes[0] / H;

    cudaFuncSetAttribute(expert_gemm, cudaFuncAttributeMaxDynamicSharedMemorySize,
                         SMEM_TOTAL);

    gate_kernel<<<(n_tokens + GTOK - 1) / GTOK, 256>>>(x, Wg, bg, We, n_tokens);
    scan_kernel<<<1, 32>>>();
    scatter_kernel<<<(n_tokens + 255) / 256, 256>>>(n_tokens);

    dim3 grid(O / BN, MAX_TILES);
    expert_gemm<<<grid, 256, SMEM_TOTAL>>>(be, out);
}

// round 10
// speedup vs baseline: 2.5388x; 1.4207x over previous
#include <cuda_runtime.h>
#include <cuda_fp16.h>
#include <cstdint>

#define H 512
#define O 512
#define E 16
#define N_MAX 32768

#define BM 128          // tokens per CTA tile
#define BN 128          // outputs per CTA tile
#define BKT 64          // fp16 k-elements per smem tile (128B per row)
#define KTILES (H / BKT)
#define MAX_TILES 272

// ---------------- device scratch ----------------
__device__ int g_eidx[N_MAX];
__device__ int g_slot[N_MAX];
__device__ int g_count[E];    // zeroed at start (static); scan re-zeroes each run
__device__ int g_ecnt[E];
__device__ int g_offset[E];
__device__ int g_perm[N_MAX];
__device__ int g_tile_e[MAX_TILES];
__device__ int g_tile_m0[MAX_TILES];
__device__ int g_ntiles;

// pre-converted fp16 copies
__device__ uint16_t g_xhi[N_MAX * H];   // 32 MB
__device__ uint16_t g_whi[E * O * H];   // 8 MB

// ---------------- helpers ----------------
__device__ __forceinline__ uint32_t smem_u32(const void* p) {
    uint32_t a;
    asm("{ .reg .u64 t; cvta.to.shared.u64 t, %1; cvt.u32.u64 %0, t; }" : "=r"(a) : "l"(p));
    return a;
}
#define SWZ(o) ((o) ^ (((o) >> 3) & 0x70))

__device__ __forceinline__ uint32_t cvt_h2(float a, float b) {
    uint32_t hi;
    asm("cvt.rn.f16x2.f32 %0, %1, %2;" : "=r"(hi) : "f"(b), "f"(a));
    return hi;
}

__device__ __forceinline__ void ldsm4(uint32_t* r, uint32_t addr) {
    asm volatile("ldmatrix.sync.aligned.m8n8.x4.shared.b16 {%0,%1,%2,%3}, [%4];"
                 : "=r"(r[0]), "=r"(r[1]), "=r"(r[2]), "=r"(r[3]) : "r"(addr));
}

__device__ __forceinline__ void mma_f16(float* d, const uint32_t* a, const uint32_t* b) {
    asm volatile(
        "mma.sync.aligned.m16n8k16.row.col.f32.f16.f16.f32 "
        "{%0,%1,%2,%3}, {%4,%5,%6,%7}, {%8,%9}, {%0,%1,%2,%3};"
        : "+f"(d[0]), "+f"(d[1]), "+f"(d[2]), "+f"(d[3])
        : "r"(a[0]), "r"(a[1]), "r"(a[2]), "r"(a[3]), "r"(b[0]), "r"(b[1]));
}

__device__ __forceinline__ void cp16(uint32_t dst, const void* src, int srcsz) {
    asm volatile("cp.async.cg.shared.global [%0], [%1], 16, %2;"
                 :: "r"(dst), "l"(src), "r"(srcsz) : "memory");
}
#define CP_COMMIT() asm volatile("cp.async.commit_group;" ::: "memory")
#define CP_WAIT(n)  asm volatile("cp.async.wait_group %0;" :: "n"(n) : "memory")

// ---------------- smem layout (GEMM): 3 stages x 32KB -> 2 CTAs/SM ----------
#define STAGE_SZ 32768
#define A_HI 0
#define B_HI 16384
#define SMEM_TOTAL (1024 + 3 * STAGE_SZ)   // 99328 -> 2 CTAs/SM
#define EPI_STRIDE 132

// ---------------- stage 1: gate + x convert + fused We convert --------------
#define GTOK 32   // tokens per block (256 threads / 8 lanes)
__global__ __launch_bounds__(256) void gate_kernel(const float* __restrict__ x,
                                                   const float* __restrict__ Wg,
                                                   const float* __restrict__ bg,
                                                   const float* __restrict__ We,
                                                   int n_tokens) {
    __shared__ float Wgs[E * H];  // 32 KB
    int t = threadIdx.x;

    // fused We -> fp16 conversion (grid-stride over 4-elem chunks)
    for (int c = blockIdx.x * 256 + t; c < E * O * H / 4; c += gridDim.x * 256) {
        int i = c * 4;
        float4 v = *(const float4*)(We + i);
        *(uint2*)(g_whi + i) = make_uint2(cvt_h2(v.x, v.y), cvt_h2(v.z, v.w));
    }

    for (int i = t; i < E * H; i += 256) Wgs[i] = Wg[i];
    __syncthreads();

    int lane8 = t & 7;
    int tok = blockIdx.x * GTOK + (t >> 3);
    if (tok >= n_tokens) return;
    const float* xr = x + (size_t)tok * H;

    float acc[E];
#pragma unroll
    for (int e = 0; e < E; e++) acc[e] = 0.f;

#pragma unroll
    for (int i = 0; i < H / 32; i++) {
        int k = i * 32 + lane8 * 4;
        float4 xv = *(const float4*)(xr + k);
        *(uint2*)(g_xhi + (size_t)tok * H + k) =
            make_uint2(cvt_h2(xv.x, xv.y), cvt_h2(xv.z, xv.w));
#pragma unroll
        for (int e = 0; e < E; e++) {
            const float* w = &Wgs[e * H + k];
            acc[e] += xv.x * w[0] + xv.y * w[1] + xv.z * w[2] + xv.w * w[3];
        }
    }

    // butterfly reduce over the 8 lanes of this token -> all 8 lanes get
    // bit-identical full logits (symmetric exchange)
#pragma unroll
    for (int e = 0; e < E; e++) {
        acc[e] += __shfl_xor_sync(0xFFFFFFFFu, acc[e], 1);
        acc[e] += __shfl_xor_sync(0xFFFFFFFFu, acc[e], 2);
        acc[e] += __shfl_xor_sync(0xFFFFFFFFu, acc[e], 4);
        acc[e] += bg[e];
    }

    // argmax + runner-up (computed identically on all 8 lanes)
    int best = 0;
    float bv = acc[0];
#pragma unroll
    for (int e = 1; e < E; e++)
        if (acc[e] > bv) { bv = acc[e]; best = e; }

    int sec = (best == 0) ? 1 : 0;
    float sv = acc[sec];
#pragma unroll
    for (int e = 0; e < E; e++)
        if (e != best && acc[e] > sv) { sv = acc[e]; sec = e; }

    if (bv - sv < 1e-3f) {
        // near-tie: 8-lane cooperative fp64 recompute of both candidates
        int ea = min(best, sec), eb = max(best, sec);
        double la = 0.0, lb = 0.0;
#pragma unroll
        for (int i = 0; i < H / 32; i++) {
            int k = i * 32 + lane8 * 4;
            float4 xv = *(const float4*)(xr + k);
            const float* wa = &Wgs[ea * H + k];
            const float* wb = &Wgs[eb * H + k];
            la += (double)xv.x * wa[0] + (double)xv.y * wa[1] +
                  (double)xv.z * wa[2] + (double)xv.w * wa[3];
            lb += (double)xv.x * wb[0] + (double)xv.y * wb[1] +
                  (double)xv.z * wb[2] + (double)xv.w * wb[3];
        }
#pragma unroll
        for (int d = 1; d < 8; d <<= 1) {
            la += __shfl_xor_sync(0xFFFFFFFFu, la, d);
            lb += __shfl_xor_sync(0xFFFFFFFFu, lb, d);
        }
        la += (double)bg[ea];
        lb += (double)bg[eb];
        best = (lb > la) ? eb : ea;  // ea wins ties (first occurrence)
    }

    if (lane8 == 0) {
        g_eidx[tok] = best;
        g_slot[tok] = atomicAdd(&g_count[best], 1);  // slot within expert
    }
}

// ---------------- stage 2: scan + tile table; self-cleans g_count ----------
__global__ void scan_kernel() {
    int lane = threadIdx.x;
    int c = (lane < E) ? g_count[lane] : 0;
    int nt = (c + BM - 1) / BM;
    int sc = c, snt = nt;
#pragma unroll
    for (int d = 1; d < 32; d <<= 1) {
        int vc = __shfl_up_sync(0xFFFFFFFFu, sc, d);
        int vn = __shfl_up_sync(0xFFFFFFFFu, snt, d);
        if (lane >= d) { sc += vc; snt += vn; }
    }
    int off = sc - c;
    int toff = snt - nt;
    if (lane < E) {
        g_offset[lane] = off;
        g_ecnt[lane] = c;
        g_count[lane] = 0;  // restore invariant for next invocation
        for (int i = 0; i < nt; i++) {
            g_tile_e[toff + i] = lane;
            g_tile_m0[toff + i] = i * BM;
        }
    }
    if (lane == 31) g_ntiles = snt;
}

// ---------------- stage 3: scatter (no atomics) ----------------
__global__ void scatter_kernel(int n_tokens) {
    int n = blockIdx.x * blockDim.x + threadIdx.x;
    if (n >= n_tokens) return;
    g_perm[g_offset[g_eidx[n]] + g_slot[n]] = n;
}

// ---------------- stage 4: fp16 HMMA gather-GEMM ----------------
__global__ __launch_bounds__(256, 2) void expert_gemm(const float* __restrict__ be,
                                                      float* __restrict__ out) {
    int tile = blockIdx.y;
    if (tile >= g_ntiles) return;
    int t = threadIdx.x;
    int e = g_tile_e[tile];
    int m0 = g_tile_m0[tile];
    int cnt = g_ecnt[e];
    int base = g_offset[e];
    int n0 = blockIdx.x * BN;

    extern __shared__ char smem[];
    int* rows = (int*)smem;
    float* bias_s = (float*)(smem + 512);
    float* stage = (float*)(smem + 1024);   // epilogue staging (aliases k-stages)
    uint32_t sb = smem_u32(smem);

    if (t < BM) {
        int m = m0 + t;
        rows[t] = (m < cnt) ? g_perm[base + m] : -1;
        bias_s[t] = be[e * O + n0 + t];
    }
    __syncthreads();

    uint32_t offA[4];
    uint32_t offB[4];
    int szA[4];
    uint32_t dsw[4];
#pragma unroll
    for (int g = 0; g < 4; g++) {
        int c = t + g * 256;
        int row = c >> 3, ch = c & 7;
        int r = rows[row];
        szA[g] = (r >= 0) ? 16 : 0;
        offA[g] = (uint32_t)(r < 0 ? 0 : r) * H + ch * 8;
        offB[g] = (uint32_t)(e * O + n0 + row) * H + ch * 8;
        dsw[g] = SWZ((uint32_t)(row * 128 + ch * 16));
    }

#define ISSUE_TILE(kt, bufbase)                                              \
    {                                                                        \
        int koff = (kt) * BKT;                                               \
        _Pragma("unroll") for (int g = 0; g < 4; g++) {                      \
            cp16((bufbase) + A_HI + dsw[g], g_xhi + offA[g] + koff, szA[g]); \
            cp16((bufbase) + B_HI + dsw[g], g_whi + offB[g] + koff, 16);     \
        }                                                                    \
        CP_COMMIT();                                                         \
    }

    int w = t >> 5, lane = t & 31;
    int warpM = w & 3, warpN = w >> 2;
    int grp = lane >> 3, lr = lane & 7;
    int arow = lr + (grp & 1) * 8;
    int akc = (grp >> 1) * 8;
    int brow = (grp >> 1) * 8 + lr;
    int bkc = (grp & 1) * 8;

    float acc[2][8][4];
#pragma unroll
    for (int i = 0; i < 2; i++)
#pragma unroll
        for (int j = 0; j < 8; j++)
#pragma unroll
            for (int c = 0; c < 4; c++) acc[i][j][c] = 0.f;

    uint32_t bufs[3] = {sb + 1024, sb + 1024 + STAGE_SZ, sb + 1024 + 2 * STAGE_SZ};

    ISSUE_TILE(0, bufs[0]);
    ISSUE_TILE(1, bufs[1]);

    for (int kt = 0; kt < KTILES; kt++) {
        if (kt < KTILES - 1) { CP_WAIT(1); } else { CP_WAIT(0); }
        __syncthreads();  // tile kt visible; reads of bufs[(kt+2)%3] (iter kt-1) done
        if (kt + 2 < KTILES) ISSUE_TILE(kt + 2, bufs[(kt + 2) % 3]);

        uint32_t bufb = bufs[kt % 3];
#pragma unroll
        for (int ks = 0; ks < 4; ks++) {
            uint32_t ah[2][4], bh[4][4];
#pragma unroll
            for (int mi = 0; mi < 2; mi++) {
                uint32_t off = SWZ((uint32_t)((warpM * 32 + mi * 16 + arow) * 128 +
                                              (ks * 16 + akc) * 2));
                ldsm4(ah[mi], bufb + A_HI + off);
            }
#pragma unroll
            for (int njp = 0; njp < 4; njp++) {
                uint32_t off = SWZ((uint32_t)((warpN * 64 + njp * 16 + brow) * 128 +
                                              (ks * 16 + bkc) * 2));
                ldsm4(bh[njp], bufb + B_HI + off);
            }
#pragma unroll
            for (int mi = 0; mi < 2; mi++)
#pragma unroll
                for (int njp = 0; njp < 4; njp++) {
                    mma_f16(acc[mi][njp * 2],     ah[mi], &bh[njp][0]);
                    mma_f16(acc[mi][njp * 2 + 1], ah[mi], &bh[njp][2]);
                }
        }
    }

    // ---- epilogue: fragments -> smem stage -> coalesced float4 stores ------
    __syncthreads();
    int qrow = lane >> 2, qcol = lane & 3;
#pragma unroll
    for (int mi = 0; mi < 2; mi++)
#pragma unroll
        for (int h = 0; h < 2; h++) {
            int m = warpM * 32 + mi * 16 + h * 8 + qrow;
            float* srow = stage + m * EPI_STRIDE + warpN * 64;
#pragma unroll
            for (int nj = 0; nj < 8; nj++) {
                int col = nj * 8 + qcol * 2;
                srow[col]     = acc[mi][nj][h * 2];
                srow[col + 1] = acc[mi][nj][h * 2 + 1];
            }
        }
    __syncthreads();

#pragma unroll
    for (int i = 0; i < 16; i++) {
        int idx = t + i * 256;
        int row = idx >> 5, c4 = idx & 31;
        int r = rows[row];
        if (r < 0) continue;
        const float* srow = stage + row * EPI_STRIDE + c4 * 4;
        float4 bv = *(const float4*)(bias_s + c4 * 4);
        float4 o;
        o.x = srow[0] + bv.x;
        o.y = srow[1] + bv.y;
        o.z = srow[2] + bv.z;
        o.w = srow[3] + bv.w;
        *(float4*)(out + (size_t)r * O + n0 + c4 * 4) = o;
    }
}

// ---------------- launch ----------------
extern "C" void kernel_launch(void* const* d_in, const int* in_sizes, int n_in,
                              void* d_out, int out_size) {
    const float* x  = (const float*)d_in[0];  // [N, H]
    const float* Wg = (const float*)d_in[1];  // [E, H]
    const float* bg = (const float*)d_in[2];  // [E]
    const float* We = (const float*)d_in[3];  // [E, O, H]
    const float* be = (const float*)d_in[4];  // [E, O]
    float* out = (float*)d_out;               // [N, O]

    int n_tokens = in_sizes[0] / H;

    cudaFuncSetAttribute(expert_gemm, cudaFuncAttributeMaxDynamicSharedMemorySize,
                         SMEM_TOTAL);

    gate_kernel<<<(n_tokens + GTOK - 1) / GTOK, 256>>>(x, Wg, bg, We, n_tokens);
    scan_kernel<<<1, 32>>>();
    scatter_kernel<<<(n_tokens + 255) / 256, 256>>>(n_tokens);

    dim3 grid(O / BN, MAX_TILES);
    expert_gemm<<<grid, 256, SMEM_TOTAL>>>(be, out);
}